// round 4
// baseline (speedup 1.0000x reference)
#include <cuda_runtime.h>

// ExpandEvecs: out[b,k,n,m] = sum_{j<=k} ev[b,n,j] * ev[b,m,j]
// ev: [B=4, C=1, N=1024, K=16] fp32 ; out: [B, K, N, N] fp32 (256 MB)
// Store-bound. Key lever this round: cut regs (118 -> ~50) by re-loading
// B-values from L1 (evb is 64KB, L1-resident) instead of caching 64 floats
// per thread -> 4 CTAs/SM resident -> 2x outstanding stores per SM.

#define NDIM 1024
#define KDIM 16
#define GRID_BLOCKS 296

__global__ __launch_bounds__(256, 4)
void expand_evecs_kernel(const float* __restrict__ ev,
                         float* __restrict__ out,
                         int n_items) {
    const int tid = threadIdx.x;
    const int m   = tid << 2;            // 4 consecutive m-columns per thread

    // Contiguous chunk of (b,n)-row work items for this block.
    const int per = n_items / GRID_BLOCKS;
    const int rem = n_items % GRID_BLOCKS;
    int start, count;
    if ((int)blockIdx.x < rem) {
        count = per + 1;
        start = blockIdx.x * count;
    } else {
        count = per;
        start = rem * (per + 1) + (blockIdx.x - rem) * per;
    }

    const size_t plane = (size_t)NDIM * NDIM;    // floats per k-plane

    for (int it = start; it < start + count; ++it) {
        const int b = it >> 10;          // NDIM = 1024
        const int n = it & (NDIM - 1);
        const float* evb = ev + (size_t)b * NDIM * KDIM;
        const float4* evb4 = (const float4*)evb;

        // a-row for this n: uniform across the block -> broadcast L1 hits.
        float a[KDIM];
        const float4* arow = (const float4*)(evb + (size_t)n * KDIM);
        #pragma unroll
        for (int q = 0; q < 4; ++q)
            ((float4*)a)[q] = __ldg(arow + q);

        float4 acc = make_float4(0.f, 0.f, 0.f, 0.f);
        float* op = out + ((size_t)b * KDIM * NDIM + n) * NDIM + m;

        #pragma unroll
        for (int kq = 0; kq < 4; ++kq) {
            // 4 B-rows' k-quad values: L1-hit LDG.128s, not register-resident.
            float4 v0 = __ldg(&evb4[(size_t)(m + 0) * 4 + kq]);
            float4 v1 = __ldg(&evb4[(size_t)(m + 1) * 4 + kq]);
            float4 v2 = __ldg(&evb4[(size_t)(m + 2) * 4 + kq]);
            float4 v3 = __ldg(&evb4[(size_t)(m + 3) * 4 + kq]);

            float vb[4][4];
            *(float4*)vb[0] = v0;
            *(float4*)vb[1] = v1;
            *(float4*)vb[2] = v2;
            *(float4*)vb[3] = v3;

            #pragma unroll
            for (int kk = 0; kk < 4; ++kk) {
                const float ak = a[kq * 4 + kk];
                acc.x = fmaf(ak, vb[0][kk], acc.x);
                acc.y = fmaf(ak, vb[1][kk], acc.y);
                acc.z = fmaf(ak, vb[2][kk], acc.z);
                acc.w = fmaf(ak, vb[3][kk], acc.w);
                __stcs((float4*)op, acc);
                op += plane;
            }
        }
    }
}

extern "C" void kernel_launch(void* const* d_in, const int* in_sizes, int n_in,
                              void* d_out, int out_size) {
    const float* ev = (const float*)d_in[0];
    float* out = (float*)d_out;
    const int B = in_sizes[0] / (NDIM * KDIM);   // = 4
    const int n_items = B * NDIM;                // 4096 (b,n) rows
    expand_evecs_kernel<<<GRID_BLOCKS, 256>>>(ev, out, n_items);
}

// round 5
// speedup vs baseline: 1.5690x; 1.5690x over previous
#include <cuda_runtime.h>

// ExpandEvecs: out[b,k,n,m] = sum_{j<=k} ev[b,n,j] * ev[b,m,j]
// ev: [B=4, C=1, N=1024, K=16] fp32 ; out: [B, K, N, N] fp32 (256 MB)
// Store-bound. This round: raise in-flight store depth.
//  - thread owns 2 m-cols -> bw regs 64->32 -> total regs < 64 -> 4 CTA/SM
//  - grid 512 blocks (64 n-tiles x 2 m-halves x 4 b): all resident in ONE
//    wave at occ 4 (512 < 148*4), no tail, 32 warps/SM issuing stores.
//  - load side ~zero like R1: B-rows in regs amortized over 16-row n-tile,
//    a-row = 4 broadcast L1-hit LDG.128 per item.

#define NDIM 1024
#define KDIM 16
#define TILE_N 16

__global__ __launch_bounds__(256, 4)
void expand_evecs_kernel(const float* __restrict__ ev, float* __restrict__ out) {
    const int b   = blockIdx.z;
    const int n0  = blockIdx.x * TILE_N;
    const int tid = threadIdx.x;
    const int m   = (blockIdx.y << 9) + (tid << 1);   // 2 consecutive m-cols

    const float* evb = ev + (size_t)b * NDIM * KDIM;
    const float4* evb4 = (const float4*)evb;

    // This thread's 2 B-rows, register-resident for the whole block.
    float bw[2][KDIM];
    #pragma unroll
    for (int i = 0; i < 2; ++i) {
        #pragma unroll
        for (int q = 0; q < 4; ++q)
            ((float4*)bw[i])[q] = evb4[(size_t)(m + i) * (KDIM / 4) + q];
    }

    float* ob = out + (size_t)b * KDIM * NDIM * NDIM;
    const size_t plane = (size_t)NDIM * NDIM;

    #pragma unroll 1
    for (int nn = 0; nn < TILE_N; ++nn) {
        const int n = n0 + nn;

        // a-row: uniform across block -> broadcast L1 hits, 4 LDG.128.
        float a[KDIM];
        const float4* arow = (const float4*)(evb + (size_t)n * KDIM);
        #pragma unroll
        for (int q = 0; q < 4; ++q)
            ((float4*)a)[q] = __ldg(arow + q);

        float2 acc = make_float2(0.f, 0.f);
        float* op = ob + (size_t)n * NDIM + m;

        #pragma unroll
        for (int k = 0; k < KDIM; ++k) {
            acc.x = fmaf(a[k], bw[0][k], acc.x);
            acc.y = fmaf(a[k], bw[1][k], acc.y);
            *(float2*)op = acc;
            op += plane;
        }
    }
}

extern "C" void kernel_launch(void* const* d_in, const int* in_sizes, int n_in,
                              void* d_out, int out_size) {
    const float* ev = (const float*)d_in[0];
    float* out = (float*)d_out;
    const int B = in_sizes[0] / (NDIM * KDIM);   // = 4
    dim3 grid(NDIM / TILE_N, 2, B);              // 64 x 2 x 4 = 512 blocks
    expand_evecs_kernel<<<grid, 256>>>(ev, out);
}

// round 6
// speedup vs baseline: 1.6347x; 1.0419x over previous
#include <cuda_runtime.h>
#include <cstdint>

// ExpandEvecs: out[b,k,n,m] = sum_{j<=k} ev[b,n,j] * ev[b,m,j]
// ev: [4,1,1024,16] fp32 ; out: [4,16,1024,1024] fp32 (256 MB)
// Store-bound at a ~4.6 TB/s STG-path ceiling -> try TMA bulk stores:
// stage each n-row's 16 k-plane segments (64KB) in smem, drain with
// cp.async.bulk (4KB contiguous per plane). 2 CTA/SM overlap compute+drain.

#define NDIM 1024
#define KDIM 16
#define GRID_BLOCKS 296
#define THREADS 256
#define BUF_BYTES (KDIM * NDIM * 4)   // 64 KB

__global__ __launch_bounds__(THREADS, 2)
void expand_evecs_tma(const float* __restrict__ ev,
                      float* __restrict__ out,
                      int n_items) {
    extern __shared__ float buf_raw[];          // [KDIM][NDIM]
    float (*buf)[NDIM] = (float (*)[NDIM])buf_raw;

    const int tid = threadIdx.x;
    const int m   = tid << 2;                   // 4 m-cols per thread

    // Contiguous chunk of (b,n) work items for this block.
    const int per = n_items / GRID_BLOCKS;
    const int rem = n_items % GRID_BLOCKS;
    int start, count;
    if ((int)blockIdx.x < rem) { count = per + 1; start = blockIdx.x * count; }
    else { count = per; start = rem * (per + 1) + (blockIdx.x - rem) * per; }

    float bw[4][KDIM];                          // register-resident B-rows
    int cur_b = -1;

    for (int it = start; it < start + count; ++it) {
        const int b = it >> 10;                 // NDIM = 1024
        const int n = it & (NDIM - 1);
        const float* evb = ev + (size_t)b * NDIM * KDIM;

        if (b != cur_b) {                       // at most 2 distinct b per block
            const float4* evb4 = (const float4*)evb;
            #pragma unroll
            for (int i = 0; i < 4; ++i) {
                #pragma unroll
                for (int q = 0; q < 4; ++q)
                    ((float4*)bw[i])[q] = evb4[(size_t)(m + i) * (KDIM / 4) + q];
            }
            cur_b = b;
        }

        // a-row: uniform across block -> broadcast L1 hits.
        float a[KDIM];
        const float4* arow = (const float4*)(evb + (size_t)n * KDIM);
        #pragma unroll
        for (int q = 0; q < 4; ++q)
            ((float4*)a)[q] = __ldg(arow + q);

        // Running cumsum over k; land each k's float4 in the row buffer.
        float4 acc = make_float4(0.f, 0.f, 0.f, 0.f);
        #pragma unroll
        for (int k = 0; k < KDIM; ++k) {
            acc.x = fmaf(a[k], bw[0][k], acc.x);
            acc.y = fmaf(a[k], bw[1][k], acc.y);
            acc.z = fmaf(a[k], bw[2][k], acc.z);
            acc.w = fmaf(a[k], bw[3][k], acc.w);
            *(float4*)&buf[k][m] = acc;
        }
        __syncthreads();                         // buffer complete

        if (tid == 0) {
            asm volatile("fence.proxy.async.shared::cta;" ::: "memory");
            #pragma unroll
            for (int k = 0; k < KDIM; ++k) {
                uint64_t gptr = (uint64_t)(out +
                    (((size_t)b * KDIM + k) * NDIM + n) * NDIM);
                uint32_t sptr = (uint32_t)__cvta_generic_to_shared(&buf[k][0]);
                asm volatile(
                    "cp.async.bulk.global.shared::cta.bulk_group [%0], [%1], %2;"
                    :: "l"(gptr), "r"(sptr), "n"(NDIM * 4) : "memory");
            }
            asm volatile("cp.async.bulk.commit_group;" ::: "memory");
            // Wait only until the engine has READ the smem (not DRAM landing).
            asm volatile("cp.async.bulk.wait_group.read 0;" ::: "memory");
        }
        __syncthreads();                         // buffer reusable
    }
}

extern "C" void kernel_launch(void* const* d_in, const int* in_sizes, int n_in,
                              void* d_out, int out_size) {
    const float* ev = (const float*)d_in[0];
    float* out = (float*)d_out;
    const int B = in_sizes[0] / (NDIM * KDIM);   // = 4
    const int n_items = B * NDIM;                // 4096 (b,n) rows

    static int attr_done = 0;
    if (!attr_done) {
        cudaFuncSetAttribute(expand_evecs_tma,
                             cudaFuncAttributeMaxDynamicSharedMemorySize,
                             BUF_BYTES);
        attr_done = 1;
    }
    expand_evecs_tma<<<GRID_BLOCKS, THREADS, BUF_BYTES>>>(ev, out, n_items);
}

// round 7
// speedup vs baseline: 1.6593x; 1.0150x over previous
#include <cuda_runtime.h>

// ExpandEvecs: out[b,k,n,m] = sum_{j<=k} ev[b,n,j] * ev[b,m,j]
// ev: [4,1,1024,16] fp32 ; out: [4,16,1024,1024] fp32 (256 MB)
// Bottleneck = steady-state HBM write drain (~5.2 TB/s observed).
// This round: k-OUTER / n-INNER loop order so each CTA writes 8 consecutive
// rows of the same k-plane back-to-back -> 32KB contiguous bursts (vs 4KB),
// targeting higher DRAM write efficiency. Cumsum kept via 8 running accs.

#define NDIM 1024
#define KDIM 16
#define TILE_N 8

__global__ __launch_bounds__(256, 2)
void expand_evecs_kernel(const float* __restrict__ ev, float* __restrict__ out) {
    const int b   = blockIdx.y;
    const int n0  = blockIdx.x * TILE_N;
    const int tid = threadIdx.x;
    const int m   = tid << 2;                 // 4 consecutive m-cols per thread

    __shared__ float a_s[TILE_N][KDIM];       // 8 x 16 a-rows for this n-tile

    const float* evb = ev + (size_t)b * NDIM * KDIM;

    // Load a-tile: 128 contiguous floats.
    if (tid < TILE_N * KDIM)
        a_s[tid >> 4][tid & 15] = evb[(size_t)n0 * KDIM + tid];

    // This thread's 4 B-rows, register-resident.
    float bw[4][KDIM];
    const float4* evb4 = (const float4*)evb;
    #pragma unroll
    for (int i = 0; i < 4; ++i) {
        #pragma unroll
        for (int q = 0; q < 4; ++q)
            ((float4*)bw[i])[q] = evb4[(size_t)(m + i) * (KDIM / 4) + q];
    }
    __syncthreads();

    // 8 running cumsum accumulators, one per n-row in the tile.
    float4 acc[TILE_N];
    #pragma unroll
    for (int nn = 0; nn < TILE_N; ++nn)
        acc[nn] = make_float4(0.f, 0.f, 0.f, 0.f);

    // Base pointer: plane k=0, row n0, col m.
    float* op = out + (((size_t)b * KDIM) * NDIM + n0) * NDIM + m;
    const size_t plane = (size_t)NDIM * NDIM;

    #pragma unroll
    for (int k = 0; k < KDIM; ++k) {
        // 8 consecutive 4KB rows of plane k -> 32KB contiguous CTA burst.
        #pragma unroll
        for (int nn = 0; nn < TILE_N; ++nn) {
            const float ak = a_s[nn][k];      // LDS broadcast
            acc[nn].x = fmaf(ak, bw[0][k], acc[nn].x);
            acc[nn].y = fmaf(ak, bw[1][k], acc[nn].y);
            acc[nn].z = fmaf(ak, bw[2][k], acc[nn].z);
            acc[nn].w = fmaf(ak, bw[3][k], acc[nn].w);
            *(float4*)(op + (size_t)nn * NDIM) = acc[nn];
        }
        op += plane;
    }
}

extern "C" void kernel_launch(void* const* d_in, const int* in_sizes, int n_in,
                              void* d_out, int out_size) {
    const float* ev = (const float*)d_in[0];
    float* out = (float*)d_out;
    const int B = in_sizes[0] / (NDIM * KDIM);   // = 4
    dim3 grid(NDIM / TILE_N, B);                 // 128 x 4 = 512 blocks
    expand_evecs_kernel<<<grid, 256>>>(ev, out);
}